// round 16
// baseline (speedup 1.0000x reference)
#include <cuda_runtime.h>
#include <cstddef>

// ---- constants ----------------------------------------------------------
constexpr int BATCH = 64;
constexpr int C13 = BATCH * 13 * 13;            // 10816
constexpr int C26 = BATCH * 26 * 26;            // 43264
constexpr int C52 = BATCH * 52 * 52;            // 173056
constexpr int TOT_CELLS = C13 + C26 + C52;      // 227136
constexpr int THREADS = 256;
constexpr int ABLK = 888;                        // assign-only blocks
constexpr int CBLK = 1480;                       // copy-only blocks
constexpr int NB   = ABLK + CBLK;                // 2368 (R12 shape: best known)

// One FCOS cell -> 25 floats into smem staging (stride-25, conflict-free).
template<int S>
__device__ __forceinline__ void assign_cell(int local,
                                            const float4* __restrict__ bboxes4,
                                            const int*    __restrict__ labels,
                                            float*        __restrict__ st)  // &stage[tid*25]
{
    const int b    = local / (S * S);
    const int cell = local % (S * S);
    const int ii = cell % S;   // x
    const int jj = cell / S;   // y

    const float stride     = 416.0f / (float)S;
    const float inv_stride = (float)S / 416.0f;   // exact (stride = 32/16/8)
    const float fii = (float)ii;
    const float fjj = (float)jj;
    const float cxc = (fii + 0.5f) * stride;
    const float cyc = (fjj + 0.5f) * stride;

    unsigned clsmask = 0u;
    float reg0 = 0.f, reg1 = 0.f, reg2 = 0.f, reg3 = 0.f, reg4 = 0.f;

    const float4* bb = bboxes4 + b * 32;
    const int*    lb = labels  + b * 32;

    #pragma unroll 4
    for (int n = 0; n < 32; ++n) {
        const float4 bx = __ldg(bb + n);
        const float cx = bx.x, cy = bx.y, bw = bx.z, bh = bx.w;

        const float pos0 = floorf(cx * inv_stride);
        const float pos1 = floorf(cy * inv_stride);
        const float bp0  = floorf(0.5f * bw * inv_stride);
        const float bp1  = floorf(0.5f * bh * inv_stride);

        const bool region = (fii >= pos0 - bp0) && (fii < pos0 + bp0) &&
                            (fjj >= pos1 - bp1) && (fjj < pos1 + bp1);

        if (region) clsmask |= (1u << __ldg(lb + n));

        const float hw = floorf(bw * 0.5f);
        const float hh = floorf(bh * 0.5f);
        const float l  = cxc - (cx - hw);
        const float r  = (cx + hw) - cxc;
        const float t  = cyc - (cy - hh);
        const float bo = (cy + hh) - cyc;

        const float mlr = fmaxf(l, r);
        const float mtb = fmaxf(t, bo);
        const float m   = fmaxf(mlr, mtb);

        bool band;
        if (S == 13)      band = (m > 256.0f);
        else if (S == 26) band = (m > 64.0f) && (m <= 256.0f);
        else              band = (m <= 64.0f);

        if (region && band) {
            const float regmax = fmaxf(fmaxf(fmaxf(reg0, reg1), fmaxf(reg2, reg3)), reg4);
            if (regmax == 0.0f || m < regmax) {
                const float cent = sqrtf(fminf(l, r) * fminf(t, bo) / (mlr * mtb));
                reg0 = fmaxf(l  * inv_stride, 0.0f);
                reg1 = fmaxf(t  * inv_stride, 0.0f);
                reg2 = fmaxf(r  * inv_stride, 0.0f);
                reg3 = fmaxf(bo * inv_stride, 0.0f);
                reg4 = fmaxf(cent, 0.0f);
            }
        }
    }

    #pragma unroll
    for (int c = 0; c < 20; ++c)
        st[c] = ((clsmask >> c) & 1u) ? 1.0f : 0.0f;
    st[20] = reg0; st[21] = reg1; st[22] = reg2; st[23] = reg3; st[24] = reg4;
}

__global__ __launch_bounds__(THREADS, 8)
void fused_kernel(const float4* __restrict__ img4,    // SM copy region base
                  float4*       __restrict__ out4,    // SM copy region base
                  int n4,                             // SM copy region size (float4)
                  const float4* __restrict__ bboxes4,
                  const int*    __restrict__ labels,
                  float*        __restrict__ out_t)   // contiguous targets (cell*25)
{
    const int bid = blockIdx.x;
    const int tid = threadIdx.x;

    if (bid < ABLK) {
        // ---- Assign-only blocks: FCOS targets, smem-staged, coalesced out ----
        __shared__ float stage[THREADS * 25];   // 25.6 KB

        const int g = bid * THREADS + tid;
        if (g < C13)              assign_cell<13>(g,             bboxes4, labels, &stage[tid * 25]);
        else if (g < C13 + C26)   assign_cell<26>(g - C13,       bboxes4, labels, &stage[tid * 25]);
        else if (g < TOT_CELLS)   assign_cell<52>(g - C13 - C26, bboxes4, labels, &stage[tid * 25]);
        __syncthreads();

        const int ncells = min(THREADS, TOT_CELLS - bid * THREADS);
        const int nf4 = (ncells * 25) / 4;                     // 1600 or 400 (both exact)
        float4* dst = reinterpret_cast<float4*>(out_t + (size_t)bid * THREADS * 25);
        const float4* src = reinterpret_cast<const float4*>(stage);
        for (int k = tid; k < nf4; k += THREADS)
            dst[k] = src[k];
    } else {
        // ---- Copy-only blocks: grid-stride float4, MLP-4 streaming ----
        const int cb = bid - ABLK;                  // 0..CBLK-1
        const int stride = CBLK * THREADS;
        int i = cb * THREADS + tid;
        for (; i + 3 * stride < n4; i += 4 * stride) {
            float4 a = __ldcs(img4 + i);
            float4 b = __ldcs(img4 + i + stride);
            float4 c = __ldcs(img4 + i + 2 * stride);
            float4 d = __ldcs(img4 + i + 3 * stride);
            __stcs(out4 + i,              a);
            __stcs(out4 + i + stride,     b);
            __stcs(out4 + i + 2 * stride, c);
            __stcs(out4 + i + 3 * stride, d);
        }
        for (; i < n4; i += stride)
            __stcs(out4 + i, __ldcs(img4 + i));
    }
}

extern "C" void kernel_launch(void* const* d_in, const int* in_sizes, int n_in,
                              void* d_out, int out_size)
{
    const float* image  = (const float*)d_in[0];
    const float* bboxes = (const float*)d_in[1];
    const int*   labels = (const int*)  d_in[2];
    float* out = (float*)d_out;

    const size_t n_img = (size_t)in_sizes[0];   // 33,226,752 floats
    const size_t half  = n_img / 2;             // 16,613,376 (divisible by 4)
    const int n4_sm = (int)((n_img - half) / 4);

    float* out_t = out + n_img;   // o13 | o26 | o52 contiguous: flat cell*25 array

    // Fork a side stream for the copy-engine branch (graph-capture-safe:
    // event fork/join creates two parallel graph branches).
    cudaStream_t s2;
    cudaStreamCreateWithFlags(&s2, cudaStreamNonBlocking);
    cudaEvent_t e0, e1;
    cudaEventCreateWithFlags(&e0, cudaEventDisableTiming);
    cudaEventCreateWithFlags(&e1, cudaEventDisableTiming);

    cudaEventRecord(e0, 0);              // fork point on the capture (legacy) stream
    cudaStreamWaitEvent(s2, e0, 0);

    // Branch A (CE): first half of the image.
    cudaMemcpyAsync(out, image, half * sizeof(float),
                    cudaMemcpyDeviceToDevice, s2);

    // Branch B (SM): second half of the image + all FCOS targets.
    fused_kernel<<<NB, THREADS>>>((const float4*)(image + half),
                                  (float4*)(out + half), n4_sm,
                                  (const float4*)bboxes, labels, out_t);

    cudaEventRecord(e1, s2);             // join
    cudaStreamWaitEvent(0, e1, 0);

    cudaEventDestroy(e0);
    cudaEventDestroy(e1);
    cudaStreamDestroy(s2);
}

// round 17
// speedup vs baseline: 1.0327x; 1.0327x over previous
#include <cuda_runtime.h>
#include <cstddef>

// ---- constants ----------------------------------------------------------
constexpr int BATCH = 64;
constexpr int C13 = BATCH * 13 * 13;            // 10816
constexpr int C26 = BATCH * 26 * 26;            // 43264
constexpr int C52 = BATCH * 52 * 52;            // 173056
constexpr int TOT_CELLS = C13 + C26 + C52;      // 227136
constexpr int THREADS = 256;
constexpr int ABLK = 888;                        // assign-only blocks (placed LAST)
constexpr int CBLK = 1480;                       // copy-only blocks (placed FIRST)
constexpr int NB   = ABLK + CBLK;                // 2368

// One FCOS cell -> 25 floats into smem staging (stride-25, conflict-free).
template<int S>
__device__ __forceinline__ void assign_cell(int local,
                                            const float4* __restrict__ bboxes4,
                                            const int*    __restrict__ labels,
                                            float*        __restrict__ st)  // &stage[tid*25]
{
    const int b    = local / (S * S);
    const int cell = local % (S * S);
    const int ii = cell % S;   // x
    const int jj = cell / S;   // y

    const float stride     = 416.0f / (float)S;
    const float inv_stride = (float)S / 416.0f;   // exact (stride = 32/16/8)
    const float fii = (float)ii;
    const float fjj = (float)jj;
    const float cxc = (fii + 0.5f) * stride;
    const float cyc = (fjj + 0.5f) * stride;

    unsigned clsmask = 0u;
    float reg0 = 0.f, reg1 = 0.f, reg2 = 0.f, reg3 = 0.f, reg4 = 0.f;

    const float4* bb = bboxes4 + b * 32;
    const int*    lb = labels  + b * 32;

    #pragma unroll 4
    for (int n = 0; n < 32; ++n) {
        const float4 bx = __ldg(bb + n);
        const float cx = bx.x, cy = bx.y, bw = bx.z, bh = bx.w;

        const float pos0 = floorf(cx * inv_stride);
        const float pos1 = floorf(cy * inv_stride);
        const float bp0  = floorf(0.5f * bw * inv_stride);
        const float bp1  = floorf(0.5f * bh * inv_stride);

        const bool region = (fii >= pos0 - bp0) && (fii < pos0 + bp0) &&
                            (fjj >= pos1 - bp1) && (fjj < pos1 + bp1);

        if (region) clsmask |= (1u << __ldg(lb + n));

        const float hw = floorf(bw * 0.5f);
        const float hh = floorf(bh * 0.5f);
        const float l  = cxc - (cx - hw);
        const float r  = (cx + hw) - cxc;
        const float t  = cyc - (cy - hh);
        const float bo = (cy + hh) - cyc;

        const float mlr = fmaxf(l, r);
        const float mtb = fmaxf(t, bo);
        const float m   = fmaxf(mlr, mtb);

        bool band;
        if (S == 13)      band = (m > 256.0f);
        else if (S == 26) band = (m > 64.0f) && (m <= 256.0f);
        else              band = (m <= 64.0f);

        if (region && band) {
            const float regmax = fmaxf(fmaxf(fmaxf(reg0, reg1), fmaxf(reg2, reg3)), reg4);
            if (regmax == 0.0f || m < regmax) {
                const float cent = sqrtf(fminf(l, r) * fminf(t, bo) / (mlr * mtb));
                reg0 = fmaxf(l  * inv_stride, 0.0f);
                reg1 = fmaxf(t  * inv_stride, 0.0f);
                reg2 = fmaxf(r  * inv_stride, 0.0f);
                reg3 = fmaxf(bo * inv_stride, 0.0f);
                reg4 = fmaxf(cent, 0.0f);
            }
        }
    }

    #pragma unroll
    for (int c = 0; c < 20; ++c)
        st[c] = ((clsmask >> c) & 1u) ? 1.0f : 0.0f;
    st[20] = reg0; st[21] = reg1; st[22] = reg2; st[23] = reg3; st[24] = reg4;
}

__global__ __launch_bounds__(THREADS)
void fused_kernel(const float4* __restrict__ img4,
                  float4*       __restrict__ out4,
                  int n4,
                  const float4* __restrict__ bboxes4,
                  const int*    __restrict__ labels,
                  float*        __restrict__ out_t)   // contiguous target region (cell*25)
{
    const int bid = blockIdx.x;
    const int tid = threadIdx.x;

    if (bid < CBLK) {
        // ---- Copy-only blocks FIRST: DRAM saturates from t=0 ----
        const int stride = CBLK * THREADS;
        int i = bid * THREADS + tid;
        for (; i + 3 * stride < n4; i += 4 * stride) {
            float4 a = __ldcs(img4 + i);
            float4 b = __ldcs(img4 + i + stride);
            float4 c = __ldcs(img4 + i + 2 * stride);
            float4 d = __ldcs(img4 + i + 3 * stride);
            __stcs(out4 + i,              a);
            __stcs(out4 + i + stride,     b);
            __stcs(out4 + i + 2 * stride, c);
            __stcs(out4 + i + 3 * stride, d);
        }
        for (; i < n4; i += stride)
            __stcs(out4 + i, __ldcs(img4 + i));
    } else {
        // ---- Assign-only blocks LAST: overlap under the copy's tail ----
        __shared__ float stage[THREADS * 25];   // 25.6 KB

        const int abid = bid - CBLK;            // 0..ABLK-1
        const int g = abid * THREADS + tid;
        if (g < C13)              assign_cell<13>(g,             bboxes4, labels, &stage[tid * 25]);
        else if (g < C13 + C26)   assign_cell<26>(g - C13,       bboxes4, labels, &stage[tid * 25]);
        else if (g < TOT_CELLS)   assign_cell<52>(g - C13 - C26, bboxes4, labels, &stage[tid * 25]);
        __syncthreads();

        const int ncells = min(THREADS, TOT_CELLS - abid * THREADS);
        const int nf4 = (ncells * 25) / 4;                     // 1600 or 400 (both exact)
        float4* dst = reinterpret_cast<float4*>(out_t + (size_t)abid * THREADS * 25);
        const float4* src = reinterpret_cast<const float4*>(stage);
        for (int k = tid; k < nf4; k += THREADS)
            dst[k] = src[k];
    }
}

extern "C" void kernel_launch(void* const* d_in, const int* in_sizes, int n_in,
                              void* d_out, int out_size)
{
    const float* image  = (const float*)d_in[0];
    const float* bboxes = (const float*)d_in[1];
    const int*   labels = (const int*)  d_in[2];
    float* out = (float*)d_out;

    const size_t n_img = (size_t)in_sizes[0];   // 33,226,752 (div by 4)
    const int n4 = (int)(n_img / 4);

    float* out_t = out + n_img;   // o13 | o26 | o52 contiguous: flat cell*25 array

    fused_kernel<<<NB, THREADS>>>((const float4*)image, (float4*)out, n4,
                                  (const float4*)bboxes, labels, out_t);
}